// round 1
// baseline (speedup 1.0000x reference)
#include <cuda_runtime.h>
#include <cstdint>

#define NB 4
#define NC 64
#define NN 4096
#define LOG2E 1.4426950408889634f
#define VS_STRIDE 68

// Scratch (allocation-free rule: __device__ globals)
__device__ __align__(16) float g_Q[NB * NN * 8];    // [b][n][8]  (pre-scaled by log2e)
__device__ __align__(16) float g_K[NB * 8 * NN];    // [b][d][n]
__device__ __align__(16) float g_V[NB * NN * NC];   // [b][n][c]  (transposed V)

__device__ __forceinline__ float fexp2(float x) {
    float r;
    asm("ex2.approx.f32 %0, %1;" : "=f"(r) : "f"(x));
    return r;
}

// ---------------------------------------------------------------------------
// Kernel 1: fused Q/K/V projections (1x1 convs). 64 pixels per block.
// ---------------------------------------------------------------------------
__global__ __launch_bounds__(256) void prep_kernel(
    const float* __restrict__ x,
    const float* __restrict__ Wq, const float* __restrict__ bq,
    const float* __restrict__ Wk, const float* __restrict__ bk,
    const float* __restrict__ Wv, const float* __restrict__ bv)
{
    __shared__ __align__(16) float xs[64 * 64];   // [c][pixel]
    __shared__ __align__(16) float ws[80 * 64];   // [o][c] fused weights
    __shared__ float bs[80];

    const int t  = threadIdx.x;
    const int b  = blockIdx.y;
    const int n0 = blockIdx.x * 64;

    for (int lin = t; lin < 80 * 64; lin += 256) {
        int o = lin >> 6, c = lin & 63;
        float w;
        if (o < 8)       w = Wq[o * 64 + c] * LOG2E;
        else if (o < 16) w = Wk[(o - 8) * 64 + c];
        else             w = Wv[(o - 16) * 64 + c];
        ws[o * 64 + c] = w;
    }
    if (t < 80) {
        float bb;
        if (t < 8)       bb = bq[t] * LOG2E;
        else if (t < 16) bb = bk[t - 8];
        else             bb = bv[t - 16];
        bs[t] = bb;
    }
    for (int lin = t; lin < 64 * 64; lin += 256) {
        int c = lin >> 6, i = lin & 63;
        xs[c * 64 + i] = x[(b * 64 + c) * NN + n0 + i];
    }
    __syncthreads();

    const int tx = t & 63;     // pixel within tile
    const int ty = t >> 6;     // 0..3 -> output group of 20

    float acc[20];
#pragma unroll
    for (int i = 0; i < 20; i++) acc[i] = 0.f;

#pragma unroll
    for (int c = 0; c < 64; c++) {
        float xv = xs[c * 64 + tx];
#pragma unroll
        for (int oo = 0; oo < 20; oo++)
            acc[oo] += ws[(ty * 20 + oo) * 64 + c] * xv;
    }

    const int n = n0 + tx;
#pragma unroll
    for (int oo = 0; oo < 20; oo++) {
        int o = ty * 20 + oo;
        float v = acc[oo] + bs[o];
        if (o < 8)       g_Q[(b * NN + n) * 8 + o] = v;
        else if (o < 16) g_K[(b * 8 + (o - 8)) * NN + n] = v;
        else             g_V[((size_t)b * NN + n) * 64 + (o - 16)] = v;
    }
}

// ---------------------------------------------------------------------------
// Kernel 2: attention. Block = 64 query rows, 8 warps x 8 rows each.
// Unnormalized softmax (energies are tiny, proven safe), one divide at end.
// ---------------------------------------------------------------------------
__global__ __launch_bounds__(256) void attn_kernel(
    const float* __restrict__ x,
    const float* __restrict__ gamma_p,
    float* __restrict__ out)
{
    __shared__ __align__(16) float sQ[64 * 8];            // 512 floats
    __shared__ __align__(16) float sV[64 * VS_STRIDE];    // 4352 floats
    __shared__ __align__(16) float sKP[512 + 8 * 8 * 64]; // Ks(512) + Ps(4096); reused as Os[64][65]
    __shared__ float sL[64];

    const int t    = threadIdx.x;
    const int lane = t & 31;
    const int w    = t >> 5;
    const int b    = blockIdx.y;
    const int qt   = blockIdx.x;

    float* Ks = sKP;
    float* Ps = sKP + 512;

    for (int lin = t; lin < 512; lin += 256)
        sQ[lin] = g_Q[(b * NN + qt * 64) * 8 + lin];

    float acc0[8], acc1[8], lpart[8];
#pragma unroll
    for (int r = 0; r < 8; r++) { acc0[r] = 0.f; acc1[r] = 0.f; lpart[r] = 0.f; }

    const float4* vsrc = (const float4*)(g_V + (size_t)b * NN * 64);
    const float*  ksrc = g_K + (size_t)b * 8 * NN;

    for (int kt = 0; kt < 64; kt++) {
        __syncthreads();   // protect sV/Ks from previous-iteration readers
        // fill V tile [64 keys][64 ch] (padded rows)
#pragma unroll
        for (int it = 0; it < 4; it++) {
            int lin = t + it * 256;
            int key = lin >> 4, q4 = lin & 15;
            float4 v = vsrc[(size_t)kt * 1024 + lin];
            *(float4*)&sV[key * VS_STRIDE + q4 * 4] = v;
        }
        // fill K tile [8][64]
#pragma unroll
        for (int it = 0; it < 2; it++) {
            int lin = t + it * 256;
            int d = lin >> 6, i = lin & 63;
            Ks[d * 64 + i] = ksrc[d * NN + kt * 64 + i];
        }
        __syncthreads();

        // --- scores + exp2 ---
        float k0[8], k1[8];
#pragma unroll
        for (int d = 0; d < 8; d++) {
            k0[d] = Ks[d * 64 + lane];
            k1[d] = Ks[d * 64 + lane + 32];
        }
#pragma unroll
        for (int r = 0; r < 8; r++) {
            const float4 qa = *(const float4*)&sQ[(w * 8 + r) * 8];
            const float4 qb = *(const float4*)&sQ[(w * 8 + r) * 8 + 4];
            float e0 = qa.x * k0[0] + qa.y * k0[1] + qa.z * k0[2] + qa.w * k0[3]
                     + qb.x * k0[4] + qb.y * k0[5] + qb.z * k0[6] + qb.w * k0[7];
            float e1 = qa.x * k1[0] + qa.y * k1[1] + qa.z * k1[2] + qa.w * k1[3]
                     + qb.x * k1[4] + qb.y * k1[5] + qb.z * k1[6] + qb.w * k1[7];
            float p0 = fexp2(e0);
            float p1 = fexp2(e1);
            lpart[r] += p0 + p1;
            Ps[(w * 8 + r) * 64 + lane]      = p0;
            Ps[(w * 8 + r) * 64 + lane + 32] = p1;
        }
        __syncwarp();

        // --- P @ V : lane owns channels (2*lane, 2*lane+1) ---
#pragma unroll
        for (int i4 = 0; i4 < 16; i4++) {
            float4 pv[8];
#pragma unroll
            for (int r = 0; r < 8; r++)
                pv[r] = *(const float4*)&Ps[(w * 8 + r) * 64 + i4 * 4];
#pragma unroll
            for (int ii = 0; ii < 4; ii++) {
                float2 v = *(const float2*)&sV[(i4 * 4 + ii) * VS_STRIDE + 2 * lane];
#pragma unroll
                for (int r = 0; r < 8; r++) {
                    float p = (ii == 0) ? pv[r].x : (ii == 1) ? pv[r].y
                            : (ii == 2) ? pv[r].z : pv[r].w;
                    acc0[r] += p * v.x;
                    acc1[r] += p * v.y;
                }
            }
        }
    }

    // --- epilogue: row-sum reduce, transpose through smem, fuse gamma*o/l + x ---
    const float gma = *gamma_p;
    __syncthreads();            // everyone done with Ks/Ps before Os overwrite
    float* Os = sKP;            // [64 ch][65]
#pragma unroll
    for (int r = 0; r < 8; r++) {
        float l = lpart[r];
#pragma unroll
        for (int off = 16; off; off >>= 1)
            l += __shfl_xor_sync(0xffffffffu, l, off);
        int jl = w * 8 + r;
        Os[(2 * lane) * 65 + jl]     = acc0[r];
        Os[(2 * lane + 1) * 65 + jl] = acc1[r];
        if (lane == 0) sL[jl] = gma / l;
    }
    __syncthreads();

    const float* xb = x   + (size_t)b * 64 * NN + qt * 64;
    float*       ob = out + (size_t)b * 64 * NN + qt * 64;
    for (int lin = t; lin < 4096; lin += 256) {
        int c = lin >> 6, jl = lin & 63;
        ob[c * NN + jl] = Os[c * 65 + jl] * sL[jl] + xb[c * NN + jl];
    }
}

// ---------------------------------------------------------------------------
extern "C" void kernel_launch(void* const* d_in, const int* in_sizes, int n_in,
                              void* d_out, int out_size) {
    (void)in_sizes; (void)n_in; (void)out_size;
    const float* x     = (const float*)d_in[0];
    const float* Wq    = (const float*)d_in[1];
    const float* bq    = (const float*)d_in[2];
    const float* Wk    = (const float*)d_in[3];
    const float* bk    = (const float*)d_in[4];
    const float* Wv    = (const float*)d_in[5];
    const float* bv    = (const float*)d_in[6];
    const float* gamma = (const float*)d_in[7];
    float* out = (float*)d_out;

    prep_kernel<<<dim3(64, NB), 256>>>(x, Wq, bq, Wk, bk, Wv, bv);
    attn_kernel<<<dim3(64, NB), 256>>>(x, gamma, out);
}

// round 3
// speedup vs baseline: 5.2035x; 5.2035x over previous
#include <cuda_runtime.h>
#include <cuda_bf16.h>
#include <cstdint>

#define NB 4
#define NN 4096
#define LOG2E 1.4426950408889634f

// ---------------- scratch (__device__ globals; no allocation) ----------------
__device__ __align__(256) __nv_bfloat16 g_Qb[NB * NN * 8];   // [b][n][8], pre-scaled by log2e
__device__ __align__(256) __nv_bfloat16 g_Kb[NB * NN * 8];   // [b][n][8]
__device__ __align__(256) __nv_bfloat16 g_Vb[NB * NN * 64];  // [b][n][64] (channel-contiguous)

// ---------------- helpers ----------------
__device__ __forceinline__ uint32_t smem_u32(const void* p) {
    uint32_t a;
    asm("{ .reg .u64 t; cvta.to.shared.u64 t, %1; cvt.u32.u64 %0, t; }" : "=r"(a) : "l"(p));
    return a;
}
__device__ __forceinline__ float fexp2(float x) {
    float r; asm("ex2.approx.f32 %0, %1;" : "=f"(r) : "f"(x)); return r;
}
__device__ __forceinline__ uint32_t pack_bf16(float lo, float hi) {
    uint32_t r; asm("cvt.rn.bf16x2.f32 %0, %1, %2;" : "=r"(r) : "f"(hi), "f"(lo)); return r;
}
__device__ __forceinline__ uint32_t swz128(uint32_t b) { return b ^ ((b >> 3) & 0x70u); }

#define CP_ASYNC16(dst, src) \
    asm volatile("cp.async.cg.shared.global [%0], [%1], 16;" :: "r"(dst), "l"(src) : "memory")
#define CP_COMMIT() asm volatile("cp.async.commit_group;" ::: "memory")
#define CP_WAIT(N)  asm volatile("cp.async.wait_group %0;" :: "n"(N) : "memory")

#define LDSM_X2(r0, r1, a) \
    asm volatile("ldmatrix.sync.aligned.m8n8.x2.shared.b16 {%0,%1}, [%2];" \
                 : "=r"(r0), "=r"(r1) : "r"(a))
#define LDSM_X4(r0, r1, r2, r3, a) \
    asm volatile("ldmatrix.sync.aligned.m8n8.x4.shared.b16 {%0,%1,%2,%3}, [%4];" \
                 : "=r"(r0), "=r"(r1), "=r"(r2), "=r"(r3) : "r"(a))
#define LDSM_X4T(r0, r1, r2, r3, a) \
    asm volatile("ldmatrix.sync.aligned.m8n8.x4.trans.shared.b16 {%0,%1,%2,%3}, [%4];" \
                 : "=r"(r0), "=r"(r1), "=r"(r2), "=r"(r3) : "r"(a))

__device__ __forceinline__ void mma_16808(float* d, uint32_t a0, uint32_t a1, uint32_t b0) {
    asm volatile("mma.sync.aligned.m16n8k8.row.col.f32.bf16.bf16.f32 "
                 "{%0,%1,%2,%3}, {%4,%5}, {%6}, {%0,%1,%2,%3};"
                 : "+f"(d[0]), "+f"(d[1]), "+f"(d[2]), "+f"(d[3])
                 : "r"(a0), "r"(a1), "r"(b0));
}
__device__ __forceinline__ void mma_16816(float* d, const uint32_t* a, uint32_t b0, uint32_t b1) {
    asm volatile("mma.sync.aligned.m16n8k16.row.col.f32.bf16.bf16.f32 "
                 "{%0,%1,%2,%3}, {%4,%5,%6,%7}, {%8,%9}, {%0,%1,%2,%3};"
                 : "+f"(d[0]), "+f"(d[1]), "+f"(d[2]), "+f"(d[3])
                 : "r"(a[0]), "r"(a[1]), "r"(a[2]), "r"(a[3]), "r"(b0), "r"(b1));
}

// ---------------------------------------------------------------------------
// Kernel 1: fused QKV projections -> bf16 in MMA-friendly layouts
// ---------------------------------------------------------------------------
__global__ __launch_bounds__(256) void prep_kernel(
    const float* __restrict__ x,
    const float* __restrict__ Wq, const float* __restrict__ bq,
    const float* __restrict__ Wk, const float* __restrict__ bk,
    const float* __restrict__ Wv, const float* __restrict__ bv)
{
    __shared__ __align__(16) float xs[64 * 64];
    __shared__ __align__(16) float ws[80 * 64];
    __shared__ float bs[80];

    const int t  = threadIdx.x;
    const int b  = blockIdx.y;
    const int n0 = blockIdx.x * 64;

    for (int lin = t; lin < 80 * 64; lin += 256) {
        int o = lin >> 6, c = lin & 63;
        float w;
        if (o < 8)       w = Wq[o * 64 + c] * LOG2E;
        else if (o < 16) w = Wk[(o - 8) * 64 + c];
        else             w = Wv[(o - 16) * 64 + c];
        ws[o * 64 + c] = w;
    }
    if (t < 80) {
        float bb;
        if (t < 8)       bb = bq[t] * LOG2E;
        else if (t < 16) bb = bk[t - 8];
        else             bb = bv[t - 16];
        bs[t] = bb;
    }
    for (int lin = t; lin < 64 * 64; lin += 256) {
        int c = lin >> 6, i = lin & 63;
        xs[c * 64 + i] = x[(b * 64 + c) * NN + n0 + i];
    }
    __syncthreads();

    const int tx = t & 63;
    const int ty = t >> 6;

    float acc[20];
#pragma unroll
    for (int i = 0; i < 20; i++) acc[i] = 0.f;
#pragma unroll
    for (int c = 0; c < 64; c++) {
        float xv = xs[c * 64 + tx];
#pragma unroll
        for (int oo = 0; oo < 20; oo++)
            acc[oo] += ws[(ty * 20 + oo) * 64 + c] * xv;
    }

    const int n = n0 + tx;
#pragma unroll
    for (int oo = 0; oo < 20; oo++) {
        int o = ty * 20 + oo;
        float v = acc[oo] + bs[o];
        __nv_bfloat16 bv16 = __float2bfloat16(v);
        if (o < 8)       g_Qb[((size_t)b * NN + n) * 8 + o] = bv16;
        else if (o < 16) g_Kb[((size_t)b * NN + n) * 8 + (o - 8)] = bv16;
        else             g_Vb[((size_t)b * NN + n) * 64 + (o - 16)] = bv16;
    }
}

// ---------------------------------------------------------------------------
// Kernel 2: flash attention via mma.sync. CTA = 128 q rows (8 warps x 16),
// key tiles of 128, P chained accumulator->A-operand (never hits smem).
// ---------------------------------------------------------------------------
// smem: sQ[128][8]bf16 (2KB); union U: K tiles 2x2KB + V tiles 2x16KB (36KB),
// reused as O staging [64][132]f32 (33.8KB) in the epilogue.
#define U_BYTES 36864
#define SV_OFF  4096

__global__ __launch_bounds__(256, 1) void attn_kernel(
    const float* __restrict__ x,
    const float* __restrict__ gamma_p,
    float* __restrict__ out)
{
    __shared__ __align__(128) __nv_bfloat16 sQ[128 * 8];
    __shared__ __align__(128) unsigned char U[U_BYTES];

    const int t    = threadIdx.x;
    const int lane = t & 31;
    const int w    = t >> 5;
    const int b    = blockIdx.y;
    const int q0   = blockIdx.x * 128;

    const uint32_t sbQ = smem_u32(sQ);
    const uint32_t sbU = smem_u32(U);

    // Q copy + tile 0 (one commit group)
    if (t < 128)
        CP_ASYNC16(sbQ + (uint32_t)t * 16u, (const char*)(g_Qb + ((size_t)b * NN + q0) * 8) + t * 16);
    {
        const char* kg = (const char*)(g_Kb + (size_t)b * NN * 8);
        const char* vg = (const char*)(g_Vb + (size_t)b * NN * 64);
        if (t < 128) CP_ASYNC16(sbU + (uint32_t)t * 16u, kg + t * 16);
#pragma unroll
        for (int i = 0; i < 4; i++) {
            int cid = t + i * 256;
            CP_ASYNC16(sbU + SV_OFF + swz128((uint32_t)cid * 16u), vg + cid * 16);
        }
    }
    CP_COMMIT();

    float o[8][4];
#pragma unroll
    for (int nt = 0; nt < 8; nt++)
#pragma unroll
        for (int i = 0; i < 4; i++) o[nt][i] = 0.f;
    float lacc0 = 0.f, lacc1 = 0.f;
    uint32_t qa0 = 0, qa1 = 0;

    for (int kt = 0; kt < 32; kt++) {
        // prefetch tile kt+1 into buffer (kt+1)&1 (safe: trailing barrier of
        // iteration kt-1 guarantees everyone is done reading that buffer)
        if (kt + 1 < 32) {
            const int buf = (kt + 1) & 1;
            const char* kg = (const char*)(g_Kb + ((size_t)b * NN + (kt + 1) * 128) * 8);
            const char* vg = (const char*)(g_Vb + ((size_t)b * NN + (kt + 1) * 128) * 64);
            if (t < 128) CP_ASYNC16(sbU + (uint32_t)buf * 2048u + (uint32_t)t * 16u, kg + t * 16);
#pragma unroll
            for (int i = 0; i < 4; i++) {
                int cid = t + i * 256;
                CP_ASYNC16(sbU + SV_OFF + (uint32_t)buf * 16384u + swz128((uint32_t)cid * 16u),
                           vg + cid * 16);
            }
            CP_COMMIT();
            CP_WAIT(1);
        } else {
            CP_WAIT(0);
        }
        __syncthreads();

        if (kt == 0) {  // Q fragment (A of m16n8k8), resident for whole loop
            uint32_t aq = sbQ + (uint32_t)(w * 16 + (lane & 15)) * 16u;
            LDSM_X2(qa0, qa1, aq);
        }

        const uint32_t sk = sbU + (uint32_t)(kt & 1) * 2048u;
        const uint32_t sv = sbU + SV_OFF + (uint32_t)(kt & 1) * 16384u;

        // K fragments: 16 x (8 keys) B-frags of m16n8k8
        uint32_t kb[16];
#pragma unroll
        for (int jj = 0; jj < 4; jj++) {
            uint32_t a = sk + (uint32_t)(jj * 32 + lane) * 16u;
            LDSM_X4(kb[4 * jj], kb[4 * jj + 1], kb[4 * jj + 2], kb[4 * jj + 3], a);
        }

#pragma unroll
        for (int h = 0; h < 2; h++) {
            // GEMM1: S(16 x 64) for keys [64h, 64h+64)
            float s[8][4];
#pragma unroll
            for (int j2 = 0; j2 < 8; j2++) {
#pragma unroll
                for (int i = 0; i < 4; i++) s[j2][i] = 0.f;
                mma_16808(s[j2], qa0, qa1, kb[8 * h + j2]);
            }
            // exp2 -> P packed directly as A-fragments of m16n8k16
            uint32_t pa[4][4];
#pragma unroll
            for (int m2 = 0; m2 < 4; m2++) {
                float* f0 = s[2 * m2];
                float* f1 = s[2 * m2 + 1];
                float e00 = fexp2(f0[0]), e01 = fexp2(f0[1]);
                float e02 = fexp2(f0[2]), e03 = fexp2(f0[3]);
                float e10 = fexp2(f1[0]), e11 = fexp2(f1[1]);
                float e12 = fexp2(f1[2]), e13 = fexp2(f1[3]);
                lacc0 += (e00 + e01) + (e10 + e11);
                lacc1 += (e02 + e03) + (e12 + e13);
                pa[m2][0] = pack_bf16(e00, e01);
                pa[m2][1] = pack_bf16(e02, e03);
                pa[m2][2] = pack_bf16(e10, e11);
                pa[m2][3] = pack_bf16(e12, e13);
            }
            // GEMM2: O(16 x 64) += P(16 x 64) @ V(64 x 64)
#pragma unroll
            for (int m2 = 0; m2 < 4; m2++) {
                const int m = 4 * h + m2;  // 16-key chunk within tile
                uint32_t vb[16];
#pragma unroll
                for (int ntp = 0; ntp < 4; ntp++) {
                    uint32_t key = (uint32_t)(16 * m + ((lane >> 3) & 1) * 8 + (lane & 7));
                    uint32_t cb  = (uint32_t)(ntp * 2 + (lane >> 4));
                    uint32_t a   = sv + swz128(key * 128u + cb * 16u);
                    LDSM_X4T(vb[4 * ntp], vb[4 * ntp + 1], vb[4 * ntp + 2], vb[4 * ntp + 3], a);
                }
#pragma unroll
                for (int nt = 0; nt < 8; nt++)
                    mma_16816(o[nt], pa[m2], vb[2 * nt], vb[2 * nt + 1]);
            }
        }
        __syncthreads();   // everyone done with buffer kt before it is refilled
    }

    // row sums: quad shfl (cols split across lanes i = lane&3)
    lacc0 += __shfl_xor_sync(0xffffffffu, lacc0, 1);
    lacc0 += __shfl_xor_sync(0xffffffffu, lacc0, 2);
    lacc1 += __shfl_xor_sync(0xffffffffu, lacc1, 1);
    lacc1 += __shfl_xor_sync(0xffffffffu, lacc1, 2);
    const float gma  = __ldg(gamma_p);
    const float inv0 = gma / lacc0;
    const float inv1 = gma / lacc1;

    // stage O (scaled) into smem [c][132], then coalesced residual-add store
    float* sO = (float*)U;
    const int r0 = w * 16 + (lane >> 2);
    const int cq = (lane & 3) * 2;
#pragma unroll
    for (int nt = 0; nt < 8; nt++) {
        int c = nt * 8 + cq;
        sO[c * 132 + r0]           = o[nt][0] * inv0;
        sO[(c + 1) * 132 + r0]     = o[nt][1] * inv0;
        sO[c * 132 + r0 + 8]       = o[nt][2] * inv1;
        sO[(c + 1) * 132 + r0 + 8] = o[nt][3] * inv1;
    }
    __syncthreads();

    for (int lin = t; lin < 64 * 32; lin += 256) {
        int c = lin >> 5, j4 = lin & 31;
        float4 v = *(const float4*)&sO[c * 132 + j4 * 4];
        size_t idx = ((size_t)b * 64 + c) * NN + q0 + j4 * 4;
        float4 xr = *(const float4*)&x[idx];
        v.x += xr.x; v.y += xr.y; v.z += xr.z; v.w += xr.w;
        *(float4*)&out[idx] = v;
    }
}

// ---------------------------------------------------------------------------
extern "C" void kernel_launch(void* const* d_in, const int* in_sizes, int n_in,
                              void* d_out, int out_size) {
    (void)in_sizes; (void)n_in; (void)out_size;
    const float* x     = (const float*)d_in[0];
    const float* Wq    = (const float*)d_in[1];
    const float* bq    = (const float*)d_in[2];
    const float* Wk    = (const float*)d_in[3];
    const float* bk    = (const float*)d_in[4];
    const float* Wv    = (const float*)d_in[5];
    const float* bv    = (const float*)d_in[6];
    const float* gamma = (const float*)d_in[7];
    float* out = (float*)d_out;

    prep_kernel<<<dim3(64, NB), 256>>>(x, Wq, bq, Wk, bk, Wv, bv);
    attn_kernel<<<dim3(32, NB), 256>>>(x, gamma, out);
}

// round 5
// speedup vs baseline: 5.2942x; 1.0174x over previous
#include <cuda_runtime.h>
#include <cuda_bf16.h>
#include <cstdint>

#define NB 4
#define NN 4096
#define LOG2E 1.4426950408889634f

// ---------------- scratch (__device__ globals; no allocation) ----------------
__device__ __align__(256) __nv_bfloat16 g_Qb[NB * NN * 8];   // [b][n][8], pre-scaled by log2e
__device__ __align__(256) __nv_bfloat16 g_Kb[NB * NN * 8];   // [b][n][8]
__device__ __align__(256) __nv_bfloat16 g_Vb[NB * NN * 64];  // [b][n][64]

// ---------------- helpers ----------------
__device__ __forceinline__ uint32_t smem_u32(const void* p) {
    uint32_t a;
    asm("{ .reg .u64 t; cvta.to.shared.u64 t, %1; cvt.u32.u64 %0, t; }" : "=r"(a) : "l"(p));
    return a;
}
__device__ __forceinline__ float fexp2(float x) {
    float r; asm("ex2.approx.f32 %0, %1;" : "=f"(r) : "f"(x)); return r;
}
__device__ __forceinline__ uint32_t pack_bf16(float lo, float hi) {
    uint32_t r; asm("cvt.rn.bf16x2.f32 %0, %1, %2;" : "=r"(r) : "f"(hi), "f"(lo)); return r;
}
__device__ __forceinline__ uint32_t swz128(uint32_t b) { return b ^ ((b >> 3) & 0x70u); }

#define CP_ASYNC16(dst, src) \
    asm volatile("cp.async.cg.shared.global [%0], [%1], 16;" :: "r"(dst), "l"(src) : "memory")
#define CP_COMMIT() asm volatile("cp.async.commit_group;" ::: "memory")
#define CP_WAIT0()  asm volatile("cp.async.wait_group 0;" ::: "memory")

#define LDSM_X2(r0, r1, a) \
    asm volatile("ldmatrix.sync.aligned.m8n8.x2.shared.b16 {%0,%1}, [%2];" \
                 : "=r"(r0), "=r"(r1) : "r"(a))
#define LDSM_X4(r0, r1, r2, r3, a) \
    asm volatile("ldmatrix.sync.aligned.m8n8.x4.shared.b16 {%0,%1,%2,%3}, [%4];" \
                 : "=r"(r0), "=r"(r1), "=r"(r2), "=r"(r3) : "r"(a))
#define LDSM_X4T(r0, r1, r2, r3, a) \
    asm volatile("ldmatrix.sync.aligned.m8n8.x4.trans.shared.b16 {%0,%1,%2,%3}, [%4];" \
                 : "=r"(r0), "=r"(r1), "=r"(r2), "=r"(r3) : "r"(a))

__device__ __forceinline__ void mma_16808(float* d, uint32_t a0, uint32_t a1, uint32_t b0) {
    asm volatile("mma.sync.aligned.m16n8k8.row.col.f32.bf16.bf16.f32 "
                 "{%0,%1,%2,%3}, {%4,%5}, {%6}, {%0,%1,%2,%3};"
                 : "+f"(d[0]), "+f"(d[1]), "+f"(d[2]), "+f"(d[3])
                 : "r"(a0), "r"(a1), "r"(b0));
}
__device__ __forceinline__ void mma_16816(float* d, const uint32_t* a, uint32_t b0, uint32_t b1) {
    asm volatile("mma.sync.aligned.m16n8k16.row.col.f32.bf16.bf16.f32 "
                 "{%0,%1,%2,%3}, {%4,%5,%6,%7}, {%8,%9}, {%0,%1,%2,%3};"
                 : "+f"(d[0]), "+f"(d[1]), "+f"(d[2]), "+f"(d[3])
                 : "r"(a[0]), "r"(a[1]), "r"(a[2]), "r"(a[3]), "r"(b0), "r"(b1));
}

// ---------------------------------------------------------------------------
// Kernel 1: fused QKV projections; staged smem epilogue -> coalesced stores
// ---------------------------------------------------------------------------
__global__ __launch_bounds__(256) void prep_kernel(
    const float* __restrict__ x,
    const float* __restrict__ Wq, const float* __restrict__ bq,
    const float* __restrict__ Wk, const float* __restrict__ bk,
    const float* __restrict__ Wv, const float* __restrict__ bv)
{
    __shared__ __align__(16) float xs[64 * 64];
    __shared__ __align__(16) float ws[80 * 64];   // weights; reused as output staging
    __shared__ float bs[80];

    const int t  = threadIdx.x;
    const int b  = blockIdx.y;
    const int n0 = blockIdx.x * 64;

    for (int lin = t; lin < 80 * 64; lin += 256) {
        int o = lin >> 6, c = lin & 63;
        float w;
        if (o < 8)       w = Wq[o * 64 + c] * LOG2E;
        else if (o < 16) w = Wk[(o - 8) * 64 + c];
        else             w = Wv[(o - 16) * 64 + c];
        ws[o * 64 + c] = w;
    }
    if (t < 80) {
        float bb;
        if (t < 8)       bb = bq[t] * LOG2E;
        else if (t < 16) bb = bk[t - 8];
        else             bb = bv[t - 16];
        bs[t] = bb;
    }
    for (int lin = t; lin < 64 * 64; lin += 256) {
        int c = lin >> 6, i = lin & 63;
        xs[c * 64 + i] = x[(b * 64 + c) * NN + n0 + i];
    }
    __syncthreads();

    const int tx = t & 63;
    const int ty = t >> 6;

    float acc[20];
#pragma unroll
    for (int i = 0; i < 20; i++) acc[i] = 0.f;
#pragma unroll
    for (int c = 0; c < 64; c++) {
        float xv = xs[c * 64 + tx];
#pragma unroll
        for (int oo = 0; oo < 20; oo++)
            acc[oo] += ws[(ty * 20 + oo) * 64 + c] * xv;
    }
    float bias[20];
#pragma unroll
    for (int oo = 0; oo < 20; oo++) bias[oo] = bs[ty * 20 + oo];

    __syncthreads();   // everyone done reading ws -> reuse as staging

    // staging layout inside ws bytes:
    //   SQ: [pixel][8ch] bf16 (1024B)   SK: same (1024B)
    //   SV: [pixel][64ch] bf16, row stride 136B (8-aligned; copied out as uint2)
    char* stage = (char*)ws;
#pragma unroll
    for (int oo = 0; oo < 20; oo++) {
        int o = ty * 20 + oo;
        __nv_bfloat16 h = __float2bfloat16(acc[oo] + bias[oo]);
        if (o < 8)
            *(__nv_bfloat16*)(stage + tx * 16 + o * 2) = h;
        else if (o < 16)
            *(__nv_bfloat16*)(stage + 1024 + tx * 16 + (o - 8) * 2) = h;
        else
            *(__nv_bfloat16*)(stage + 2048 + tx * 136 + (o - 16) * 2) = h;
    }
    __syncthreads();

    // coalesced copy-out (Q/K as 16B, V as 8B chunks — 136B rows are 8-aligned)
    if (t < 64) {
        *(uint4*)(g_Qb + ((size_t)b * NN + n0 + t) * 8) = *(const uint4*)(stage + t * 16);
    } else if (t < 128) {
        int i = t - 64;
        *(uint4*)(g_Kb + ((size_t)b * NN + n0 + i) * 8) = *(const uint4*)(stage + 1024 + i * 16);
    }
#pragma unroll
    for (int i = 0; i < 4; i++) {
        int lin = t + i * 256;               // 1024 chunks of 8B
        int pix = lin >> 4, chk = lin & 15;
        *(uint2*)(g_Vb + ((size_t)b * NN + n0 + pix) * 64 + chk * 4) =
            *(const uint2*)(stage + 2048 + pix * 136 + chk * 8);
    }
}

// ---------------------------------------------------------------------------
// Kernel 2: flash attention, mma.sync. CTA = 64 queries, 8 warps:
// rowgrp = w&3 (16 rows), keyhalf = w>>2 (2048 keys each). 64-key tiles,
// double-buffered cp.async, ONE barrier per tile. P stays in registers.
// ---------------------------------------------------------------------------
#define STG_B 18432u   // per-stage bytes: K 2x1KB + V 2x8KB
#define U_BYTES 36864

__global__ __launch_bounds__(256, 2) void attn_kernel(
    const float* __restrict__ x,
    const float* __restrict__ gamma_p,
    float* __restrict__ out)
{
    __shared__ __align__(128) __nv_bfloat16 sQ[64 * 8];
    __shared__ __align__(128) unsigned char U[U_BYTES];

    const int t      = threadIdx.x;
    const int lane   = t & 31;
    const int w      = t >> 5;
    const int rowgrp = w & 3;
    const int khalf  = w >> 2;
    const int b      = blockIdx.y;
    const int q0     = blockIdx.x * 64;

    const uint32_t sbQ = smem_u32(sQ);
    const uint32_t sbU = smem_u32(U);

    // cp.async roles (constant over iterations)
    const int kc_half = t >> 6;            // t<128: which K half
    const int kc_key  = t & 63;
    const __nv_bfloat16* kg_base = g_Kb + ((size_t)b * NN + kc_half * 2048 + kc_key) * 8;
    const uint32_t k_dst_off = (uint32_t)kc_half * 1024u + (uint32_t)kc_key * 16u;

    // tile 0 + Q, one group
    if (t < 64)
        CP_ASYNC16(sbQ + (uint32_t)t * 16u, (const char*)(g_Qb + ((size_t)b * NN + q0 + t) * 8));
    if (t < 128)
        CP_ASYNC16(sbU + k_dst_off, (const char*)kg_base);
#pragma unroll
    for (int i = 0; i < 4; i++) {
        int cid = t + i * 256;                       // [half][key][chk]
        int vh = cid >> 9, vk = (cid >> 3) & 63, vc = cid & 7;
        CP_ASYNC16(sbU + 2048u + (uint32_t)vh * 8192u + swz128((uint32_t)vk * 128u + (uint32_t)vc * 16u),
                   (const char*)(g_Vb + ((size_t)b * NN + vh * 2048 + vk) * 64 + vc * 8));
    }
    CP_COMMIT();

    float o[8][4];
#pragma unroll
    for (int nt = 0; nt < 8; nt++)
#pragma unroll
        for (int i = 0; i < 4; i++) o[nt][i] = 0.f;
    float lacc0 = 0.f, lacc1 = 0.f;
    uint32_t qa0 = 0, qa1 = 0;

    for (int it = 0; it < 32; it++) {
        const uint32_t buf = (uint32_t)(it & 1) * STG_B;
        CP_WAIT0();
        __syncthreads();   // tile `it` visible AND everyone done with buf^1

        if (it + 1 < 32) {  // prefetch it+1 into the other buffer
            const uint32_t pbuf = (uint32_t)((it + 1) & 1) * STG_B;
            const int nk = (it + 1) * 64;
            if (t < 128)
                CP_ASYNC16(sbU + pbuf + k_dst_off, (const char*)(kg_base + (size_t)nk * 8));
#pragma unroll
            for (int i = 0; i < 4; i++) {
                int cid = t + i * 256;
                int vh = cid >> 9, vk = (cid >> 3) & 63, vc = cid & 7;
                CP_ASYNC16(sbU + pbuf + 2048u + (uint32_t)vh * 8192u + swz128((uint32_t)vk * 128u + (uint32_t)vc * 16u),
                           (const char*)(g_Vb + ((size_t)b * NN + vh * 2048 + (it + 1) * 64 + vk) * 64 + vc * 8));
            }
            CP_COMMIT();
        }

        if (it == 0) {   // Q fragment, resident for whole loop
            LDSM_X2(qa0, qa1, sbQ + (uint32_t)(rowgrp * 16 + (lane & 15)) * 16u);
        }

        const uint32_t kb_base = sbU + buf + (uint32_t)khalf * 1024u;
        const uint32_t vb_base = sbU + buf + 2048u + (uint32_t)khalf * 8192u;

        uint32_t kb[8];
        LDSM_X4(kb[0], kb[1], kb[2], kb[3], kb_base + (uint32_t)lane * 16u);
        LDSM_X4(kb[4], kb[5], kb[6], kb[7], kb_base + (uint32_t)(32 + lane) * 16u);

#pragma unroll
        for (int m = 0; m < 4; m++) {   // 16-key chunks
            float s[8];
#pragma unroll
            for (int i = 0; i < 8; i++) s[i] = 0.f;
            mma_16808(s,     qa0, qa1, kb[2 * m]);
            mma_16808(s + 4, qa0, qa1, kb[2 * m + 1]);

            float e0 = fexp2(s[0]), e1 = fexp2(s[1]), e2 = fexp2(s[2]), e3 = fexp2(s[3]);
            float e4 = fexp2(s[4]), e5 = fexp2(s[5]), e6 = fexp2(s[6]), e7 = fexp2(s[7]);
            lacc0 += (e0 + e1) + (e4 + e5);
            lacc1 += (e2 + e3) + (e6 + e7);
            uint32_t pa[4];
            pa[0] = pack_bf16(e0, e1);
            pa[1] = pack_bf16(e2, e3);
            pa[2] = pack_bf16(e4, e5);
            pa[3] = pack_bf16(e6, e7);

            uint32_t vb[16];
            const uint32_t vkey = (uint32_t)(16 * m + ((lane >> 3) & 1) * 8 + (lane & 7));
#pragma unroll
            for (int ntp = 0; ntp < 4; ntp++) {
                uint32_t cb = (uint32_t)(ntp * 2 + (lane >> 4));
                LDSM_X4T(vb[4 * ntp], vb[4 * ntp + 1], vb[4 * ntp + 2], vb[4 * ntp + 3],
                         vb_base + swz128(vkey * 128u + cb * 16u));
            }
#pragma unroll
            for (int nt = 0; nt < 8; nt++)
                mma_16816(o[nt], pa, vb[2 * nt], vb[2 * nt + 1]);
        }
    }

    // ---- epilogue: combine key-halves through smem ----
    lacc0 += __shfl_xor_sync(0xffffffffu, lacc0, 1);
    lacc0 += __shfl_xor_sync(0xffffffffu, lacc0, 2);
    lacc1 += __shfl_xor_sync(0xffffffffu, lacc1, 1);
    lacc1 += __shfl_xor_sync(0xffffffffu, lacc1, 2);
    const float gma = __ldg(gamma_p);

    __syncthreads();   // done with K/V tiles; reuse U

    float* sOh = (float*)U;                 // [64 rows][66] raw partials (keyhalf 1)
    float* sLh = (float*)(U + 16896);       // [64] partial row sums
    float* sO  = (float*)(U + 17168);       // [64 ch][68] final staged

    const int r0 = rowgrp * 16 + (lane >> 2);
    const int cq = (lane & 3) * 2;

    if (khalf == 1) {
#pragma unroll
        for (int nt = 0; nt < 8; nt++) {
            int c = nt * 8 + cq;
            sOh[r0 * 66 + c]           = o[nt][0];
            sOh[r0 * 66 + c + 1]       = o[nt][1];
            sOh[(r0 + 8) * 66 + c]     = o[nt][2];
            sOh[(r0 + 8) * 66 + c + 1] = o[nt][3];
        }
        if ((lane & 3) == 0) { sLh[r0] = lacc0; sLh[r0 + 8] = lacc1; }
    }
    __syncthreads();

    if (khalf == 0) {
        const float inv0 = gma / (lacc0 + sLh[r0]);
        const float inv1 = gma / (lacc1 + sLh[r0 + 8]);
#pragma unroll
        for (int nt = 0; nt < 8; nt++) {
            int c = nt * 8 + cq;
            sO[c * 68 + r0]           = (o[nt][0] + sOh[r0 * 66 + c])           * inv0;
            sO[(c + 1) * 68 + r0]     = (o[nt][1] + sOh[r0 * 66 + c + 1])       * inv0;
            sO[c * 68 + r0 + 8]       = (o[nt][2] + sOh[(r0 + 8) * 66 + c])     * inv1;
            sO[(c + 1) * 68 + r0 + 8] = (o[nt][3] + sOh[(r0 + 8) * 66 + c + 1]) * inv1;
        }
    }
    __syncthreads();

    // coalesced residual-add store: 64 ch x 64 q
    for (int lin = t; lin < 64 * 16; lin += 256) {
        int c = lin >> 4, j4 = lin & 15;
        float4 v = *(const float4*)&sO[c * 68 + j4 * 4];
        size_t idx = ((size_t)b * 64 + c) * NN + q0 + j4 * 4;
        float4 xr = *(const float4*)&x[idx];
        v.x += xr.x; v.y += xr.y; v.z += xr.z; v.w += xr.w;
        *(float4*)&out[idx] = v;
    }
}

// ---------------------------------------------------------------------------
extern "C" void kernel_launch(void* const* d_in, const int* in_sizes, int n_in,
                              void* d_out, int out_size) {
    (void)in_sizes; (void)n_in; (void)out_size;
    const float* x     = (const float*)d_in[0];
    const float* Wq    = (const float*)d_in[1];
    const float* bq    = (const float*)d_in[2];
    const float* Wk    = (const float*)d_in[3];
    const float* bk    = (const float*)d_in[4];
    const float* Wv    = (const float*)d_in[5];
    const float* bv    = (const float*)d_in[6];
    const float* gamma = (const float*)d_in[7];
    float* out = (float*)d_out;

    prep_kernel<<<dim3(64, NB), 256>>>(x, Wq, bq, Wk, bk, Wv, bv);
    attn_kernel<<<dim3(64, NB), 256>>>(x, gamma, out);
}

// round 6
// speedup vs baseline: 5.3518x; 1.0109x over previous
#include <cuda_runtime.h>
#include <cuda_fp16.h>
#include <cstdint>

#define NB 4
#define NN 4096
#define LOG2E 1.4426950408889634f

// ---------------- scratch (__device__ globals; no allocation) ----------------
__device__ __align__(256) __half g_Qh[NB * NN * 8];   // [b][n][8], pre-scaled by log2e
__device__ __align__(256) __half g_Kh[NB * NN * 8];   // [b][n][8]
__device__ __align__(256) __half g_Vh[NB * NN * 64];  // [b][n][64]

// ---------------- helpers ----------------
__device__ __forceinline__ uint32_t smem_u32(const void* p) {
    uint32_t a;
    asm("{ .reg .u64 t; cvta.to.shared.u64 t, %1; cvt.u32.u64 %0, t; }" : "=r"(a) : "l"(p));
    return a;
}
__device__ __forceinline__ uint32_t swz128(uint32_t b) { return b ^ ((b >> 3) & 0x70u); }

#define CP_ASYNC16(dst, src) \
    asm volatile("cp.async.cg.shared.global [%0], [%1], 16;" :: "r"(dst), "l"(src) : "memory")
#define CP_COMMIT() asm volatile("cp.async.commit_group;" ::: "memory")
#define CP_WAIT0()  asm volatile("cp.async.wait_group 0;" ::: "memory")

#define LDSM_X4(r0, r1, r2, r3, a) \
    asm volatile("ldmatrix.sync.aligned.m8n8.x4.shared.b16 {%0,%1,%2,%3}, [%4];" \
                 : "=r"(r0), "=r"(r1), "=r"(r2), "=r"(r3) : "r"(a))
#define LDSM_X4T(r0, r1, r2, r3, a) \
    asm volatile("ldmatrix.sync.aligned.m8n8.x4.trans.shared.b16 {%0,%1,%2,%3}, [%4];" \
                 : "=r"(r0), "=r"(r1), "=r"(r2), "=r"(r3) : "r"(a))

// S(16x8,f16) = Q(16x8,f16) @ K^T ; C = 0
__device__ __forceinline__ void mma16808h(uint32_t* d, uint32_t a0, uint32_t a1, uint32_t b0) {
    uint32_t z = 0;
    asm volatile("mma.sync.aligned.m16n8k8.row.col.f16.f16.f16.f16 "
                 "{%0,%1}, {%2,%3}, {%4}, {%5,%5};"
                 : "=r"(d[0]), "=r"(d[1]) : "r"(a0), "r"(a1), "r"(b0), "r"(z));
}
// O(16x8,f16) += P(16x16,f16) @ V(16x8,f16)
__device__ __forceinline__ void mma16816h(uint32_t* d, const uint32_t* a, uint32_t b0, uint32_t b1) {
    asm volatile("mma.sync.aligned.m16n8k16.row.col.f16.f16.f16.f16 "
                 "{%0,%1}, {%2,%3,%4,%5}, {%6,%7}, {%0,%1};"
                 : "+r"(d[0]), "+r"(d[1])
                 : "r"(a[0]), "r"(a[1]), "r"(a[2]), "r"(a[3]), "r"(b0), "r"(b1));
}
#define EX2H2(r) asm volatile("ex2.approx.f16x2 %0, %0;" : "+r"(r))
__device__ __forceinline__ uint32_t hadd2u(uint32_t a, uint32_t b) {
    uint32_t d; asm("add.rn.f16x2 %0, %1, %2;" : "=r"(d) : "r"(a), "r"(b)); return d;
}
__device__ __forceinline__ float h2sumf(uint32_t r) {
    __half2 h = *reinterpret_cast<__half2*>(&r);
    return __low2float(h) + __high2float(h);
}

// ---------------------------------------------------------------------------
// Kernel 1: fused QKV projections (f16 outputs, staged coalesced stores)
// ---------------------------------------------------------------------------
__global__ __launch_bounds__(256) void prep_kernel(
    const float* __restrict__ x,
    const float* __restrict__ Wq, const float* __restrict__ bq,
    const float* __restrict__ Wk, const float* __restrict__ bk,
    const float* __restrict__ Wv, const float* __restrict__ bv)
{
    __shared__ __align__(16) float xs[64 * 64];
    __shared__ __align__(16) float ws[80 * 64];   // weights; reused as output staging
    __shared__ float bs[80];

    const int t  = threadIdx.x;
    const int b  = blockIdx.y;
    const int n0 = blockIdx.x * 64;

    for (int lin = t; lin < 80 * 64; lin += 256) {
        int o = lin >> 6, c = lin & 63;
        float w;
        if (o < 8)       w = Wq[o * 64 + c] * LOG2E;
        else if (o < 16) w = Wk[(o - 8) * 64 + c];
        else             w = Wv[(o - 16) * 64 + c];
        ws[o * 64 + c] = w;
    }
    if (t < 80) {
        float bb;
        if (t < 8)       bb = bq[t] * LOG2E;
        else if (t < 16) bb = bk[t - 8];
        else             bb = bv[t - 16];
        bs[t] = bb;
    }
    for (int lin = t; lin < 64 * 64; lin += 256) {
        int c = lin >> 6, i = lin & 63;
        xs[c * 64 + i] = x[(b * 64 + c) * NN + n0 + i];
    }
    __syncthreads();

    const int tx = t & 63;
    const int ty = t >> 6;

    float acc[20];
#pragma unroll
    for (int i = 0; i < 20; i++) acc[i] = 0.f;
#pragma unroll
    for (int c = 0; c < 64; c++) {
        float xv = xs[c * 64 + tx];
#pragma unroll
        for (int oo = 0; oo < 20; oo++)
            acc[oo] += ws[(ty * 20 + oo) * 64 + c] * xv;
    }
    float bias[20];
#pragma unroll
    for (int oo = 0; oo < 20; oo++) bias[oo] = bs[ty * 20 + oo];

    __syncthreads();   // done reading ws -> reuse as staging

    // staging: SQ [pix][8ch] (1024B) | SK same (1024B) | SV [pix][64ch], 136B rows
    char* stage = (char*)ws;
#pragma unroll
    for (int oo = 0; oo < 20; oo++) {
        int o = ty * 20 + oo;
        __half h = __float2half(acc[oo] + bias[oo]);
        if (o < 8)
            *(__half*)(stage + tx * 16 + o * 2) = h;
        else if (o < 16)
            *(__half*)(stage + 1024 + tx * 16 + (o - 8) * 2) = h;
        else
            *(__half*)(stage + 2048 + tx * 136 + (o - 16) * 2) = h;
    }
    __syncthreads();

    if (t < 64) {
        *(uint4*)(g_Qh + ((size_t)b * NN + n0 + t) * 8) = *(const uint4*)(stage + t * 16);
    } else if (t < 128) {
        int i = t - 64;
        *(uint4*)(g_Kh + ((size_t)b * NN + n0 + i) * 8) = *(const uint4*)(stage + 1024 + i * 16);
    }
#pragma unroll
    for (int i = 0; i < 4; i++) {
        int lin = t + i * 256;               // 1024 chunks of 8B
        int pix = lin >> 4, chk = lin & 15;
        *(uint2*)(g_Vh + ((size_t)b * NN + n0 + pix) * 64 + chk * 4) =
            *(const uint2*)(stage + 2048 + pix * 136 + chk * 8);
    }
}

// ---------------------------------------------------------------------------
// Kernel 2: flash attention, all-f16 mma.sync.
// CTA = 64 queries, 8 warps: rowgrp = w>>2 (32 rows), kq = w&3 (1024 keys).
// 128-key tiles per iter, double-buffered cp.async, one barrier per iter.
// S-regs -> ex2.f16x2 in place -> directly the A-fragment of GEMM2.
// ---------------------------------------------------------------------------
#define SM_K0 0u
#define SM_K1 2048u
#define SM_V0 4096u
#define SM_V1 20480u
#define SM_L  32768u      // epilogue: float[4][64]
#define U_BYTES 36864

__global__ __launch_bounds__(256, 2) void attn_kernel(
    const float* __restrict__ x,
    const float* __restrict__ gamma_p,
    float* __restrict__ out)
{
    __shared__ __align__(128) __half sQ[64 * 8];
    __shared__ __align__(1024) unsigned char U[U_BYTES];

    const int t      = threadIdx.x;
    const int lane   = t & 31;
    const int w      = t >> 5;
    const int rowgrp = w >> 2;          // 0,1 -> rows [32*rowgrp, +32)
    const int kq     = w & 3;           // key quarter within each 128-key tile
    const int b      = blockIdx.y;
    const int q0     = blockIdx.x * 64;

    const uint32_t sbQ = smem_u32(sQ);
    const uint32_t sbU = smem_u32(U);

    // PDL: wait for prep_kernel before touching its outputs
    cudaGridDependencySynchronize();

    // initial loads: Q + tile 0
    if (t < 64)
        CP_ASYNC16(sbQ + (uint32_t)t * 16u, (const char*)(g_Qh + ((size_t)b * NN + q0 + t) * 8));
    if (t < 128)
        CP_ASYNC16(sbU + SM_K0 + (uint32_t)t * 16u, (const char*)(g_Kh + ((size_t)b * NN + t) * 8));
#pragma unroll
    for (int i = 0; i < 4; i++) {
        int cid = t + i * 256;                  // 1024 chunks: key = cid>>3, chk = cid&7
        int vk = cid >> 3, vc = cid & 7;
        CP_ASYNC16(sbU + SM_V0 + swz128((uint32_t)vk * 128u + (uint32_t)vc * 16u),
                   (const char*)(g_Vh + ((size_t)b * NN + vk) * 64 + vc * 8));
    }
    CP_COMMIT();

    uint32_t o[2][16];                          // [rowfrag][nt*2+d] f16x2 accumulators
#pragma unroll
    for (int rf = 0; rf < 2; rf++)
#pragma unroll
        for (int i = 0; i < 16; i++) o[rf][i] = 0u;
    float lacc[4] = {0.f, 0.f, 0.f, 0.f};       // row sums: [rf*2+d]
    uint32_t qa[4] = {0u, 0u, 0u, 0u};

    for (int it = 0; it < 32; it++) {
        CP_WAIT0();
        __syncthreads();        // tile `it` visible; everyone done with other buffer

        if (it + 1 < 32) {      // prefetch next tile
            const int nb = (it + 1) & 1;
            const uint32_t kdst = sbU + (nb ? SM_K1 : SM_K0);
            const uint32_t vdst = sbU + (nb ? SM_V1 : SM_V0);
            const int kbase = (it + 1) * 128;
            if (t < 128)
                CP_ASYNC16(kdst + (uint32_t)t * 16u,
                           (const char*)(g_Kh + ((size_t)b * NN + kbase + t) * 8));
#pragma unroll
            for (int i = 0; i < 4; i++) {
                int cid = t + i * 256;
                int vk = cid >> 3, vc = cid & 7;
                CP_ASYNC16(vdst + swz128((uint32_t)vk * 128u + (uint32_t)vc * 16u),
                           (const char*)(g_Vh + ((size_t)b * NN + kbase + vk) * 64 + vc * 8));
            }
            CP_COMMIT();
        }

        if (it == 0) {  // Q A-frags for 32 rows, resident all loop
            LDSM_X4(qa[0], qa[1], qa[2], qa[3], sbQ + (uint32_t)(rowgrp * 32 + lane) * 16u);
        }

        const uint32_t kbuf = sbU + ((it & 1) ? SM_K1 : SM_K0);
        const uint32_t vbuf = sbU + ((it & 1) ? SM_V1 : SM_V0);

        uint32_t kb[4];     // 32 keys (this quarter)
        LDSM_X4(kb[0], kb[1], kb[2], kb[3], kbuf + (uint32_t)(kq * 32 + lane) * 16u);

#pragma unroll
        for (int m = 0; m < 2; m++) {   // two 16-key chunks
            // GEMM1 -> S (f16), rowfrag 0 and 1
            uint32_t p0[4], p1[4];
            mma16808h(p0,     qa[0], qa[1], kb[2 * m]);
            mma16808h(p0 + 2, qa[0], qa[1], kb[2 * m + 1]);
            mma16808h(p1,     qa[2], qa[3], kb[2 * m]);
            mma16808h(p1 + 2, qa[2], qa[3], kb[2 * m + 1]);

            // exp2 in place: S-regs become P A-fragments
            EX2H2(p0[0]); EX2H2(p0[1]); EX2H2(p0[2]); EX2H2(p0[3]);
            EX2H2(p1[0]); EX2H2(p1[1]); EX2H2(p1[2]); EX2H2(p1[3]);

            // fold row sums to f32 (d0 regs: rows r; d1 regs: rows r+8)
            lacc[0] += h2sumf(hadd2u(p0[0], p0[2]));
            lacc[1] += h2sumf(hadd2u(p0[1], p0[3]));
            lacc[2] += h2sumf(hadd2u(p1[0], p1[2]));
            lacc[3] += h2sumf(hadd2u(p1[1], p1[3]));

            // V B-frags: 16 keys x 64 ch
            uint32_t vb[16];
            const uint32_t vkey = (uint32_t)(kq * 32 + m * 16 + ((lane >> 3) & 1) * 8 + (lane & 7));
#pragma unroll
            for (int ntp = 0; ntp < 4; ntp++) {
                uint32_t cb = (uint32_t)(ntp * 2 + (lane >> 4));
                LDSM_X4T(vb[4 * ntp], vb[4 * ntp + 1], vb[4 * ntp + 2], vb[4 * ntp + 3],
                         vbuf + swz128(vkey * 128u + cb * 16u));
            }
            // GEMM2: O += P @ V  (f16 acc, 2 regs per 16x8 tile)
#pragma unroll
            for (int nt = 0; nt < 8; nt++) {
                mma16816h(&o[0][2 * nt], p0, vb[2 * nt], vb[2 * nt + 1]);
                mma16816h(&o[1][2 * nt], p1, vb[2 * nt], vb[2 * nt + 1]);
            }
        }
    }

    // ---- epilogue: combine 4 key-quarters through smem ----
#pragma unroll
    for (int j = 0; j < 4; j++) {
        lacc[j] += __shfl_xor_sync(0xffffffffu, lacc[j], 1);
        lacc[j] += __shfl_xor_sync(0xffffffffu, lacc[j], 2);
    }
    const float gma = __ldg(gamma_p);

    __syncthreads();            // all loop reads of U done

    __half* sOp = (__half*)U;               // [kq][ch 64][q 64] f16 partials (32KB)
    float*  sL  = (float*)(U + SM_L);       // [kq][64] partial row sums

    if ((lane & 3) == 0) {
#pragma unroll
        for (int j = 0; j < 4; j++) {       // j = rf*2 + d -> row offset rf*16 + d*8
            int row = rowgrp * 32 + (j >> 1) * 16 + (j & 1) * 8 + (lane >> 2);
            sL[kq * 64 + row] = lacc[j];
        }
    }
#pragma unroll
    for (int rf = 0; rf < 2; rf++)
#pragma unroll
        for (int nt = 0; nt < 8; nt++)
#pragma unroll
            for (int d = 0; d < 2; d++) {
                __half2 hv = *reinterpret_cast<__half2*>(&o[rf][nt * 2 + d]);
                int row = rowgrp * 32 + rf * 16 + d * 8 + (lane >> 2);
                int c0  = nt * 8 + (lane & 3) * 2;
                sOp[(kq * 64 + c0) * 64 + row]       = __low2half(hv);
                sOp[(kq * 64 + c0 + 1) * 64 + row]   = __high2half(hv);
            }
    __syncthreads();

    // final: thread owns q = t&63, channels (t>>6) + 4*i
    {
        const int q = t & 63;
        const float l = sL[q] + sL[64 + q] + sL[128 + q] + sL[192 + q];
        const float inv = gma / l;
#pragma unroll
        for (int i = 0; i < 16; i++) {
            int c = (t >> 6) + 4 * i;
            float acc = (float)sOp[(0 * 64 + c) * 64 + q] + (float)sOp[(1 * 64 + c) * 64 + q]
                      + (float)sOp[(2 * 64 + c) * 64 + q] + (float)sOp[(3 * 64 + c) * 64 + q];
            size_t idx = ((size_t)b * 64 + c) * NN + q0 + q;
            out[idx] = acc * inv + x[idx];
        }
    }
}

// ---------------------------------------------------------------------------
extern "C" void kernel_launch(void* const* d_in, const int* in_sizes, int n_in,
                              void* d_out, int out_size) {
    (void)in_sizes; (void)n_in; (void)out_size;
    const float* x     = (const float*)d_in[0];
    const float* Wq    = (const float*)d_in[1];
    const float* bq    = (const float*)d_in[2];
    const float* Wk    = (const float*)d_in[3];
    const float* bk    = (const float*)d_in[4];
    const float* Wv    = (const float*)d_in[5];
    const float* bv    = (const float*)d_in[6];
    const float* gamma = (const float*)d_in[7];
    float* out = (float*)d_out;

    prep_kernel<<<dim3(64, NB), 256>>>(x, Wq, bq, Wk, bk, Wv, bv);

    // attn with programmatic stream serialization (overlaps launch with prep tail)
    cudaLaunchConfig_t cfg = {};
    cfg.gridDim  = dim3(64, NB);
    cfg.blockDim = dim3(256);
    cfg.dynamicSmemBytes = 0;
    cfg.stream = 0;
    cudaLaunchAttribute attrs[1];
    attrs[0].id = cudaLaunchAttributeProgrammaticStreamSerialization;
    attrs[0].val.programmaticStreamSerializationAllowed = 1;
    cfg.attrs = attrs;
    cfg.numAttrs = 1;
    cudaLaunchKernelEx(&cfg, attn_kernel, x, gamma, out);
}

// round 8
// speedup vs baseline: 5.5088x; 1.0293x over previous
#include <cuda_runtime.h>
#include <cuda_fp16.h>
#include <cstdint>

#define NB 4
#define NN 4096
#define LOG2E 1.4426950408889634f

// ---------------- scratch (__device__ globals; no allocation) ----------------
__device__ __align__(256) __half g_Qh[NB * NN * 8];   // [b][n][8], pre-scaled by log2e
__device__ __align__(256) __half g_Kh[NB * NN * 8];   // [b][n][8]
__device__ __align__(256) __half g_Vh[NB * NN * 64];  // [b][n][64]

// ---------------- helpers ----------------
__device__ __forceinline__ uint32_t smem_u32(const void* p) {
    uint32_t a;
    asm("{ .reg .u64 t; cvta.to.shared.u64 t, %1; cvt.u32.u64 %0, t; }" : "=r"(a) : "l"(p));
    return a;
}
__device__ __forceinline__ uint32_t swz128(uint32_t b) { return b ^ ((b >> 3) & 0x70u); }

#define CP_ASYNC16(dst, src) \
    asm volatile("cp.async.cg.shared.global [%0], [%1], 16;" :: "r"(dst), "l"(src) : "memory")
#define CP_COMMIT() asm volatile("cp.async.commit_group;" ::: "memory")
#define CP_WAIT0()  asm volatile("cp.async.wait_group 0;" ::: "memory")

#define LDSM_X4(r0, r1, r2, r3, a) \
    asm volatile("ldmatrix.sync.aligned.m8n8.x4.shared.b16 {%0,%1,%2,%3}, [%4];" \
                 : "=r"(r0), "=r"(r1), "=r"(r2), "=r"(r3) : "r"(a))
#define LDSM_X4T(r0, r1, r2, r3, a) \
    asm volatile("ldmatrix.sync.aligned.m8n8.x4.trans.shared.b16 {%0,%1,%2,%3}, [%4];" \
                 : "=r"(r0), "=r"(r1), "=r"(r2), "=r"(r3) : "r"(a))

// S(16x8,f16) = Q(16x8,f16) @ K^T ; C = 0
__device__ __forceinline__ void mma16808h(uint32_t* d, uint32_t a0, uint32_t a1, uint32_t b0) {
    uint32_t z = 0;
    asm volatile("mma.sync.aligned.m16n8k8.row.col.f16.f16.f16.f16 "
                 "{%0,%1}, {%2,%3}, {%4}, {%5,%5};"
                 : "=r"(d[0]), "=r"(d[1]) : "r"(a0), "r"(a1), "r"(b0), "r"(z));
}
// O(16x8,f16) += P(16x16,f16) @ V(16x8,f16)
__device__ __forceinline__ void mma16816h(uint32_t* d, const uint32_t* a, uint32_t b0, uint32_t b1) {
    asm volatile("mma.sync.aligned.m16n8k16.row.col.f16.f16.f16.f16 "
                 "{%0,%1}, {%2,%3,%4,%5}, {%6,%7}, {%0,%1};"
                 : "+r"(d[0]), "+r"(d[1])
                 : "r"(a[0]), "r"(a[1]), "r"(a[2]), "r"(a[3]), "r"(b0), "r"(b1));
}
#define EX2H2(r) asm volatile("ex2.approx.f16x2 %0, %0;" : "+r"(r))
__device__ __forceinline__ uint32_t hadd2u(uint32_t a, uint32_t b) {
    uint32_t d; asm("add.rn.f16x2 %0, %1, %2;" : "=r"(d) : "r"(a), "r"(b)); return d;
}
__device__ __forceinline__ float h2sumf(uint32_t r) {
    __half2 h = *reinterpret_cast<__half2*>(&r);
    return __low2float(h) + __high2float(h);
}

// ---------------------------------------------------------------------------
// Kernel 1: fused QKV projections (f16 outputs, staged coalesced stores)
// ---------------------------------------------------------------------------
__global__ __launch_bounds__(256) void prep_kernel(
    const float* __restrict__ x,
    const float* __restrict__ Wq, const float* __restrict__ bq,
    const float* __restrict__ Wk, const float* __restrict__ bk,
    const float* __restrict__ Wv, const float* __restrict__ bv)
{
    __shared__ __align__(16) float xs[64 * 64];
    __shared__ __align__(16) float ws[80 * 64];   // weights; reused as output staging
    __shared__ float bs[80];

    const int t  = threadIdx.x;
    const int b  = blockIdx.y;
    const int n0 = blockIdx.x * 64;

    for (int lin = t; lin < 80 * 64; lin += 256) {
        int o = lin >> 6, c = lin & 63;
        float w;
        if (o < 8)       w = Wq[o * 64 + c] * LOG2E;
        else if (o < 16) w = Wk[(o - 8) * 64 + c];
        else             w = Wv[(o - 16) * 64 + c];
        ws[o * 64 + c] = w;
    }
    if (t < 80) {
        float bb;
        if (t < 8)       bb = bq[t] * LOG2E;
        else if (t < 16) bb = bk[t - 8];
        else             bb = bv[t - 16];
        bs[t] = bb;
    }
    for (int lin = t; lin < 64 * 64; lin += 256) {
        int c = lin >> 6, i = lin & 63;
        xs[c * 64 + i] = x[(b * 64 + c) * NN + n0 + i];
    }
    __syncthreads();

    const int tx = t & 63;
    const int ty = t >> 6;

    float acc[20];
#pragma unroll
    for (int i = 0; i < 20; i++) acc[i] = 0.f;
#pragma unroll
    for (int c = 0; c < 64; c++) {
        float xv = xs[c * 64 + tx];
#pragma unroll
        for (int oo = 0; oo < 20; oo++)
            acc[oo] += ws[(ty * 20 + oo) * 64 + c] * xv;
    }
    float bias[20];
#pragma unroll
    for (int oo = 0; oo < 20; oo++) bias[oo] = bs[ty * 20 + oo];

    __syncthreads();   // done reading ws -> reuse as staging

    // staging: SQ [pix][8ch] (1024B) | SK same (1024B) | SV [pix][64ch], 136B rows
    char* stage = (char*)ws;
#pragma unroll
    for (int oo = 0; oo < 20; oo++) {
        int o = ty * 20 + oo;
        __half h = __float2half(acc[oo] + bias[oo]);
        if (o < 8)
            *(__half*)(stage + tx * 16 + o * 2) = h;
        else if (o < 16)
            *(__half*)(stage + 1024 + tx * 16 + (o - 8) * 2) = h;
        else
            *(__half*)(stage + 2048 + tx * 136 + (o - 16) * 2) = h;
    }
    __syncthreads();

    if (t < 64) {
        *(uint4*)(g_Qh + ((size_t)b * NN + n0 + t) * 8) = *(const uint4*)(stage + t * 16);
    } else if (t < 128) {
        int i = t - 64;
        *(uint4*)(g_Kh + ((size_t)b * NN + n0 + i) * 8) = *(const uint4*)(stage + 1024 + i * 16);
    }
#pragma unroll
    for (int i = 0; i < 4; i++) {
        int lin = t + i * 256;               // 1024 chunks of 8B
        int pix = lin >> 4, chk = lin & 15;
        *(uint2*)(g_Vh + ((size_t)b * NN + n0 + pix) * 64 + chk * 4) =
            *(const uint2*)(stage + 2048 + pix * 136 + chk * 8);
    }
}

// ---------------------------------------------------------------------------
// Kernel 2: flash attention, all-f16 mma.sync, phase-overlapped inner loop.
// CTA = 64 queries, 8 warps: rowgrp = w>>2 (32 rows), kq = w&3 (1024 keys).
// 128-key tiles, double-buffered cp.async, one barrier per iter.
// ---------------------------------------------------------------------------
#define SM_K0 0u
#define SM_K1 2048u
#define SM_V0 4096u
#define SM_V1 20480u
#define SM_L  32768u      // epilogue: float[4][64]
#define U_BYTES 36864

__global__ __launch_bounds__(256, 2) void attn_kernel(
    const float* __restrict__ x,
    const float* __restrict__ gamma_p,
    float* __restrict__ out)
{
    __shared__ __align__(128) __half sQ[64 * 8];
    __shared__ __align__(1024) unsigned char U[U_BYTES];

    const int t      = threadIdx.x;
    const int lane   = t & 31;
    const int w      = t >> 5;
    const int rowgrp = w >> 2;          // 0,1 -> rows [32*rowgrp, +32)
    const int kq     = w & 3;           // key quarter within each 128-key tile
    const int b      = blockIdx.y;
    const int q0     = blockIdx.x * 64;

    const uint32_t sbQ = smem_u32(sQ);
    const uint32_t sbU = smem_u32(U);

    // PDL: wait for prep_kernel before touching its outputs
    cudaGridDependencySynchronize();

    // initial loads: Q + tile 0
    if (t < 64)
        CP_ASYNC16(sbQ + (uint32_t)t * 16u, (const char*)(g_Qh + ((size_t)b * NN + q0 + t) * 8));
    if (t < 128)
        CP_ASYNC16(sbU + SM_K0 + (uint32_t)t * 16u, (const char*)(g_Kh + ((size_t)b * NN + t) * 8));
#pragma unroll
    for (int i = 0; i < 4; i++) {
        int cid = t + i * 256;                  // 1024 chunks: key = cid>>3, chk = cid&7
        int vk = cid >> 3, vc = cid & 7;
        CP_ASYNC16(sbU + SM_V0 + swz128((uint32_t)vk * 128u + (uint32_t)vc * 16u),
                   (const char*)(g_Vh + ((size_t)b * NN + vk) * 64 + vc * 8));
    }
    CP_COMMIT();

    uint32_t o[2][16];                          // [rowfrag][nt*2+d] f16x2 accumulators
#pragma unroll
    for (int rf = 0; rf < 2; rf++)
#pragma unroll
        for (int i = 0; i < 16; i++) o[rf][i] = 0u;
    float lacc[4] = {0.f, 0.f, 0.f, 0.f};       // row sums: [rf*2+d]
    uint32_t qa[4];

    // peel: tile 0 + Q ready; load Q A-frags once
    CP_WAIT0();
    __syncthreads();
    LDSM_X4(qa[0], qa[1], qa[2], qa[3], sbQ + (uint32_t)(rowgrp * 32 + lane) * 16u);

    for (int it = 0; it < 32; it++) {
        if (it + 1 < 32) {      // prefetch next tile into other buffer
            const int nb = (it + 1) & 1;
            const uint32_t kdst = sbU + (nb ? SM_K1 : SM_K0);
            const uint32_t vdst = sbU + (nb ? SM_V1 : SM_V0);
            const int kbase = (it + 1) * 128;
            if (t < 128)
                CP_ASYNC16(kdst + (uint32_t)t * 16u,
                           (const char*)(g_Kh + ((size_t)b * NN + kbase + t) * 8));
#pragma unroll
            for (int i = 0; i < 4; i++) {
                int cid = t + i * 256;
                int vk = cid >> 3, vc = cid & 7;
                CP_ASYNC16(vdst + swz128((uint32_t)vk * 128u + (uint32_t)vc * 16u),
                           (const char*)(g_Vh + ((size_t)b * NN + kbase + vk) * 64 + vc * 8));
            }
            CP_COMMIT();
        }

        const uint32_t kbuf = sbU + ((it & 1) ? SM_K1 : SM_K0);
        const uint32_t vbuf = sbU + ((it & 1) ? SM_V1 : SM_V0);

        uint32_t kb[4];     // 32 keys (this warp's quarter)
        LDSM_X4(kb[0], kb[1], kb[2], kb[3], kbuf + (uint32_t)(kq * 32 + lane) * 16u);

        // ---- issue ALL MMA1s up front (both 16-key chunks) ----
        uint32_t sA[8], sB[8];
        mma16808h(sA + 0, qa[0], qa[1], kb[0]);
        mma16808h(sA + 2, qa[0], qa[1], kb[1]);
        mma16808h(sA + 4, qa[2], qa[3], kb[0]);
        mma16808h(sA + 6, qa[2], qa[3], kb[1]);
        mma16808h(sB + 0, qa[0], qa[1], kb[2]);
        mma16808h(sB + 2, qa[0], qa[1], kb[3]);
        mma16808h(sB + 4, qa[2], qa[3], kb[2]);
        mma16808h(sB + 6, qa[2], qa[3], kb[3]);

        // ---- chunk A: EX2 (overlaps MMA1(B) on tensor) -> LDSM V -> MMA2 ----
        EX2H2(sA[0]); EX2H2(sA[1]); EX2H2(sA[2]); EX2H2(sA[3]);
        EX2H2(sA[4]); EX2H2(sA[5]); EX2H2(sA[6]); EX2H2(sA[7]);
        {
            uint32_t vb[16];
            const uint32_t vkey = (uint32_t)(kq * 32 + ((lane >> 3) & 1) * 8 + (lane & 7));
#pragma unroll
            for (int ntp = 0; ntp < 4; ntp++) {
                uint32_t cb = (uint32_t)(ntp * 2 + (lane >> 4));
                LDSM_X4T(vb[4 * ntp], vb[4 * ntp + 1], vb[4 * ntp + 2], vb[4 * ntp + 3],
                         vbuf + swz128(vkey * 128u + cb * 16u));
            }
#pragma unroll
            for (int nt = 0; nt < 8; nt++) {
                mma16816h(&o[0][2 * nt], sA + 0, vb[2 * nt], vb[2 * nt + 1]);
                mma16816h(&o[1][2 * nt], sA + 4, vb[2 * nt], vb[2 * nt + 1]);
            }
        }

        // ---- chunk B: EX2 (overlaps MMA2(A) tensor burst) -> LDSM V -> MMA2 ----
        EX2H2(sB[0]); EX2H2(sB[1]); EX2H2(sB[2]); EX2H2(sB[3]);
        EX2H2(sB[4]); EX2H2(sB[5]); EX2H2(sB[6]); EX2H2(sB[7]);
        {
            uint32_t vb[16];
            const uint32_t vkey = (uint32_t)(kq * 32 + 16 + ((lane >> 3) & 1) * 8 + (lane & 7));
#pragma unroll
            for (int ntp = 0; ntp < 4; ntp++) {
                uint32_t cb = (uint32_t)(ntp * 2 + (lane >> 4));
                LDSM_X4T(vb[4 * ntp], vb[4 * ntp + 1], vb[4 * ntp + 2], vb[4 * ntp + 3],
                         vbuf + swz128(vkey * 128u + cb * 16u));
            }
#pragma unroll
            for (int nt = 0; nt < 8; nt++) {
                mma16816h(&o[0][2 * nt], sB + 0, vb[2 * nt], vb[2 * nt + 1]);
                mma16816h(&o[1][2 * nt], sB + 4, vb[2 * nt], vb[2 * nt + 1]);
            }
        }

        // ---- row sums (off critical path; overlaps MMA2(B) drain) ----
        lacc[0] += h2sumf(hadd2u(sA[0], sA[2])) + h2sumf(hadd2u(sB[0], sB[2]));
        lacc[1] += h2sumf(hadd2u(sA[1], sA[3])) + h2sumf(hadd2u(sB[1], sB[3]));
        lacc[2] += h2sumf(hadd2u(sA[4], sA[6])) + h2sumf(hadd2u(sB[4], sB[6]));
        lacc[3] += h2sumf(hadd2u(sA[5], sA[7])) + h2sumf(hadd2u(sB[5], sB[7]));

        if (it + 1 < 32) {
            CP_WAIT0();
            __syncthreads();    // next tile visible; everyone done with its buffer
        }
    }

    // ---- epilogue: combine 4 key-quarters through smem ----
#pragma unroll
    for (int j = 0; j < 4; j++) {
        lacc[j] += __shfl_xor_sync(0xffffffffu, lacc[j], 1);
        lacc[j] += __shfl_xor_sync(0xffffffffu, lacc[j], 2);
    }
    const float gma = __ldg(gamma_p);

    __syncthreads();            // all loop reads of U done

    __half* sOp = (__half*)U;               // [kq][ch 64][q 64] f16 partials (32KB)
    float*  sL  = (float*)(U + SM_L);       // [kq][64] partial row sums

    if ((lane & 3) == 0) {
#pragma unroll
        for (int j = 0; j < 4; j++) {       // j = rf*2 + d -> row offset rf*16 + d*8
            int row = rowgrp * 32 + (j >> 1) * 16 + (j & 1) * 8 + (lane >> 2);
            sL[kq * 64 + row] = lacc[j];
        }
    }
#pragma unroll
    for (int rf = 0; rf < 2; rf++)
#pragma unroll
        for (int nt = 0; nt < 8; nt++)
#pragma unroll
            for (int d = 0; d < 2; d++) {
                __half2 hv = *reinterpret_cast<__half2*>(&o[rf][nt * 2 + d]);
                int row = rowgrp * 32 + rf * 16 + d * 8 + (lane >> 2);
                int c0  = nt * 8 + (lane & 3) * 2;
                sOp[(kq * 64 + c0) * 64 + row]       = __low2half(hv);
                sOp[(kq * 64 + c0 + 1) * 64 + row]   = __high2half(hv);
            }
    __syncthreads();

    // final: thread owns q = t&63, channels (t>>6) + 4*i
    {
        const int q = t & 63;
        const float l = sL[q] + sL[64 + q] + sL[128 + q] + sL[192 + q];
        const float inv = gma / l;
#pragma unroll
        for (int i = 0; i < 16; i++) {
            int c = (t >> 6) + 4 * i;
            float acc = (float)sOp[(0 * 64 + c) * 64 + q] + (float)sOp[(1 * 64 + c) * 64 + q]
                      + (float)sOp[(2 * 64 + c) * 64 + q] + (float)sOp[(3 * 64 + c) * 64 + q];
            size_t idx = ((size_t)b * 64 + c) * NN + q0 + q;
            out[idx] = acc * inv + x[idx];
        }
    }
}

// ---------------------------------------------------------------------------
extern "C" void kernel_launch(void* const* d_in, const int* in_sizes, int n_in,
                              void* d_out, int out_size) {
    (void)in_sizes; (void)n_in; (void)out_size;
    const float* x     = (const float*)d_in[0];
    const float* Wq    = (const float*)d_in[1];
    const float* bq    = (const float*)d_in[2];
    const float* Wk    = (const float*)d_in[3];
    const float* bk    = (const float*)d_in[4];
    const float* Wv    = (const float*)d_in[5];
    const float* bv    = (const float*)d_in[6];
    const float* gamma = (const float*)d_in[7];
    float* out = (float*)d_out;

    prep_kernel<<<dim3(64, NB), 256>>>(x, Wq, bq, Wk, bk, Wv, bv);

    // attn with programmatic stream serialization
    cudaLaunchConfig_t cfg = {};
    cfg.gridDim  = dim3(64, NB);
    cfg.blockDim = dim3(256);
    cfg.dynamicSmemBytes = 0;
    cfg.stream = 0;
    cudaLaunchAttribute attrs[1];
    attrs[0].id = cudaLaunchAttributeProgrammaticStreamSerialization;
    attrs[0].val.programmaticStreamSerializationAllowed = 1;
    cfg.attrs = attrs;
    cfg.numAttrs = 1;
    cudaLaunchKernelEx(&cfg, attn_kernel, x, gamma, out);
}